// round 2
// baseline (speedup 1.0000x reference)
#include <cuda_runtime.h>
#include <math.h>

#define IN_SIZE  256
#define N_NODES  512
#define OUT_SIZE 64
#define TT       2048
#define DD       832          // IN_SIZE + N_NODES + OUT_SIZE
#define FAN_IN   32
#define GD       768          // IN_SIZE + N_NODES (max gather index range)

// ---------------- device scratch (no allocations allowed) ----------------
__device__ float g_actT[GD * TT];        // actT[d][t] = actives[t+1][d], t in [0,2047)
__device__ float g_K[N_NODES * TT];      // K[ix][t] for t<2047 (slot 2047 zero/unused)
__device__ float g_V[N_NODES * TT];
__device__ float g_kmax[N_NODES];
__device__ float g_kmin[N_NODES];

// ---------------- Phase A: shifted transpose ----------------
// actT[d][t] = actives[t+1][d]  (coalesced reads along d; scattered L2 writes)
__global__ void transpose_kernel(const float* __restrict__ actives) {
    int t = blockIdx.y;                                  // 0..2046
    int d = blockIdx.x * blockDim.x + threadIdx.x;
    if (d < GD) g_actT[d * TT + t] = actives[(t + 1) * DD + d];
}

// ---------------- Phase B: per-node K/V precompute + kmin/kmax ----------------
__global__ void __launch_bounds__(256) precompute_kernel(
    const float* __restrict__ weights, const int* __restrict__ in_idxs) {
    int ix  = blockIdx.x;
    int tid = threadIdx.x;
    __shared__ int   s_idx[FAN_IN];
    __shared__ float s_w1[FAN_IN], s_w2[FAN_IN];
    __shared__ float s_red[16];

    if (tid < FAN_IN) {
        s_idx[tid] = in_idxs[ix * FAN_IN + tid];
        s_w1[tid]  = weights[(ix * FAN_IN + tid) * 3 + 1];
        s_w2[tid]  = weights[(ix * FAN_IN + tid) * 3 + 2];
    }
    __syncthreads();

    float kmax = -INFINITY, kmin = INFINITY;
    for (int t = tid; t < TT; t += 256) {
        if (t < TT - 1) {
            float k = 0.f, v = 0.f;
            #pragma unroll
            for (int j = 0; j < FAN_IN; j++) {
                float a = g_actT[s_idx[j] * TT + t];   // coalesced along t
                k += a * s_w1[j];
                v += a * s_w2[j];
            }
            g_K[ix * TT + t] = k;
            g_V[ix * TT + t] = v;
            kmax = fmaxf(kmax, k);
            kmin = fminf(kmin, k);
        } else {
            g_K[ix * TT + t] = 0.f;                    // padded slot, masked in phase 2
            g_V[ix * TT + t] = 0.f;
        }
    }
    // block reduce kmax/kmin
    #pragma unroll
    for (int o = 16; o > 0; o >>= 1) {
        kmax = fmaxf(kmax, __shfl_xor_sync(0xFFFFFFFFu, kmax, o));
        kmin = fminf(kmin, __shfl_xor_sync(0xFFFFFFFFu, kmin, o));
    }
    int w = tid >> 5;
    if ((tid & 31) == 0) { s_red[w] = kmax; s_red[8 + w] = kmin; }
    __syncthreads();
    if (tid == 0) {
        float mx = s_red[0], mn = s_red[8];
        #pragma unroll
        for (int i = 1; i < 8; i++) { mx = fmaxf(mx, s_red[i]); mn = fminf(mn, s_red[8 + i]); }
        g_kmax[ix] = mx;
        g_kmin[ix] = mn;
    }
}

// ---------------- Phase C: sequential 512-node scan, single persistent block ----------------
__global__ void __launch_bounds__(256) seq_kernel(
    const float* __restrict__ x,
    const float* __restrict__ weights,
    const int*  __restrict__ in_idxs,
    float* __restrict__ out)
{
    __shared__ float s_row[GD];            // last row (only d<768 is ever gathered)
    __shared__ float s_pe [2][8];          // double-buffered per-warp partials
    __shared__ float s_pev[2][8];

    int tid  = threadIdx.x;
    int lane = tid & 31;
    int warp = tid >> 5;

    for (int d = tid; d < GD; d += 256)
        s_row[d] = (d < IN_SIZE) ? x[d] : 0.f;
    __syncthreads();

    // ---- preload node 0 ----
    int   nidx = in_idxs[lane];
    float nw0  = weights[lane * 3 + 0];
    float nw1  = weights[lane * 3 + 1];
    float nw2  = weights[lane * 3 + 2];
    float4 nk0 = *(const float4*)&g_K[tid * 8];
    float4 nk1 = *(const float4*)&g_K[tid * 8 + 4];
    float4 nv0 = *(const float4*)&g_V[tid * 8];
    float4 nv1 = *(const float4*)&g_V[tid * 8 + 4];
    float nkmx = g_kmax[0], nkmn = g_kmin[0];

    float out_prev = 0.f;

    for (int ix = 0; ix < N_NODES; ix++) {
        // rotate prefetched -> current
        int   cidx = nidx;
        float w0 = nw0, w1 = nw1, w2 = nw2;
        float4 k0 = nk0, k1 = nk1, v0 = nv0, v1 = nv1;
        float kmx = nkmx, kmn = nkmn;

        // gather input from shared last-row; patch the one element written last step
        float a = s_row[cidx];
        if (ix > 0 && cidx == IN_SIZE + (ix - 1)) a = out_prev;
        if (tid == 0 && ix > 0) s_row[IN_SIZE + (ix - 1)] = out_prev;  // ordered by the bar below

        // q, k_last, v_last — redundant per-warp butterfly reductions (no publish/bar needed)
        float p0 = a * w0, p1 = a * w1, p2 = a * w2;
        #pragma unroll
        for (int o = 16; o > 0; o >>= 1) {
            p0 += __shfl_xor_sync(0xFFFFFFFFu, p0, o);
            p1 += __shfl_xor_sync(0xFFFFFFFFu, p1, o);
            p2 += __shfl_xor_sync(0xFFFFFFFFu, p2, o);
        }
        float q = p0, kl = p1, vl = p2;
        // exact softmax max: max_t(q*k_t) = q*kmax (q>=0) else q*kmin; include the live t=2047 term
        float maxl = fmaxf((q >= 0.f) ? q * kmx : q * kmn, q * kl);

        // prefetch next node while the softmax math runs (K/V independent of the scan)
        if (ix + 1 < N_NODES) {
            int b = ix + 1;
            nidx = in_idxs[b * FAN_IN + lane];
            nw0  = weights[(b * FAN_IN + lane) * 3 + 0];
            nw1  = weights[(b * FAN_IN + lane) * 3 + 1];
            nw2  = weights[(b * FAN_IN + lane) * 3 + 2];
            nk0 = *(const float4*)&g_K[b * TT + tid * 8];
            nk1 = *(const float4*)&g_K[b * TT + tid * 8 + 4];
            nv0 = *(const float4*)&g_V[b * TT + tid * 8];
            nv1 = *(const float4*)&g_V[b * TT + tid * 8 + 4];
            nkmx = g_kmax[b];
            nkmn = g_kmin[b];
        }

        // 8 exps per thread over register-resident K/V
        float kk[8] = {k0.x, k0.y, k0.z, k0.w, k1.x, k1.y, k1.z, k1.w};
        float vv[8] = {v0.x, v0.y, v0.z, v0.w, v1.x, v1.y, v1.z, v1.w};
        float se = 0.f, sev = 0.f;
        #pragma unroll
        for (int i = 0; i < 8; i++) {
            float e = __expf(q * kk[i] - maxl);
            if (tid * 8 + i == TT - 1) e = 0.f;   // padded slot (t=2047 handled via kl/vl)
            se  += e;
            sev += e * vv[i];
        }
        #pragma unroll
        for (int o = 16; o > 0; o >>= 1) {
            se  += __shfl_xor_sync(0xFFFFFFFFu, se,  o);
            sev += __shfl_xor_sync(0xFFFFFFFFu, sev, o);
        }
        int pb = ix & 1;
        if (lane == 0) { s_pe[pb][warp] = se; s_pev[pb][warp] = sev; }
        __syncthreads();   // the ONLY bar per node (also orders the s_row update)

        // all threads redundantly finish: combine 8 warp partials + the live t=2047 term
        float tse  = __expf(q * kl - maxl);
        float tsev = tse * vl;
        #pragma unroll
        for (int i = 0; i < 8; i++) { tse += s_pe[pb][i]; tsev += s_pev[pb][i]; }

        float r  = __fdividef(tsev, tse);
        float y  = __expf(2.f * r);
        float ov = 1.f - __fdividef(2.f, y + 1.f);   // tanh(r), robust at +/-inf
        out_prev = ov;

        if (ix >= N_NODES - OUT_SIZE && tid == 0)
            out[ix - (N_NODES - OUT_SIZE)] = ov;
    }
}

// ---------------- launch ----------------
extern "C" void kernel_launch(void* const* d_in, const int* in_sizes, int n_in,
                              void* d_out, int out_size) {
    const float* x       = (const float*)d_in[0];
    const float* actives = (const float*)d_in[1];
    const float* weights = (const float*)d_in[2];
    const int*   in_idxs = (const int*)  d_in[3];
    float* out = (float*)d_out;

    dim3 tgrid((GD + 255) / 256, TT - 1);
    transpose_kernel<<<tgrid, 256>>>(actives);
    precompute_kernel<<<N_NODES, 256>>>(weights, in_idxs);
    seq_kernel<<<1, 256>>>(x, weights, in_idxs, out);
}